// round 4
// baseline (speedup 1.0000x reference)
#include <cuda_runtime.h>
#include <cstddef>

#define NN 50000
#define EE 800000
// DV=128, DE=64, DH=64, 3*DH=192

// ---------------- scratch ----------------
__device__ float g_QKV[(size_t)NN * 192];   // [N][Q|K|V]  38.4 MB
__device__ float g_Z[(size_t)EE * 192];     // zij         614 MB
__device__ float g_S[(size_t)EE * 192];     // sigmoid(LN(aij)) 614 MB

// ---------------- K1: QKV projection ----------------
// out[n][t] = node_fea[n] @ [WQ|WK|WV][:,t] + b, t in [0,192)
__global__ void k_qkv(const float* __restrict__ node_fea,
                      const float* __restrict__ WQ, const float* __restrict__ bQ,
                      const float* __restrict__ WK, const float* __restrict__ bK,
                      const float* __restrict__ WV, const float* __restrict__ bV) {
    extern __shared__ float sm[];
    float* Ws = sm;              // [128][192]
    float* bs = Ws + 128 * 192;  // [192]
    float* xs = bs + 192;        // [128]
    int t = threadIdx.x;
    for (int i = t; i < 128 * 64; i += blockDim.x) {
        int k = i >> 6, j = i & 63;
        Ws[k * 192 + j]       = WQ[i];
        Ws[k * 192 + 64 + j]  = WK[i];
        Ws[k * 192 + 128 + j] = WV[i];
    }
    for (int j = t; j < 64; j += blockDim.x) {
        bs[j] = bQ[j]; bs[64 + j] = bK[j]; bs[128 + j] = bV[j];
    }
    __syncthreads();
    for (int n = blockIdx.x; n < NN; n += gridDim.x) {
        if (t < 128) xs[t] = node_fea[(size_t)n * 128 + t];
        __syncthreads();
        if (t < 192) {
            float acc = bs[t];
            #pragma unroll 16
            for (int k = 0; k < 128; k++) acc = fmaf(xs[k], Ws[k * 192 + t], acc);
            g_QKV[(size_t)n * 192 + t] = acc;
        }
        __syncthreads();
    }
}

// ---------------- K2: per-edge gather, Ep, LN(aij), sigmoid ----------------
// warp per edge. grid = EE/8 blocks of 256.
__global__ void k_edge(const int* __restrict__ idx1,
                       const int* __restrict__ idx2,
                       const float* __restrict__ edge_fea,
                       const float* __restrict__ WE, const float* __restrict__ bE,
                       const float* __restrict__ g1, const float* __restrict__ b1) {
    __shared__ float WEs[64 * 64];
    __shared__ float bEs[64];
    __shared__ float g1s[192], b1s[192];
    __shared__ float efs[8][64];
    int t = threadIdx.x, w = t >> 5, l = t & 31;
    for (int i = t; i < 64 * 64; i += blockDim.x) WEs[i] = WE[i];
    for (int i = t; i < 64; i += blockDim.x) bEs[i] = bE[i];
    for (int i = t; i < 192; i += blockDim.x) { g1s[i] = g1[i]; b1s[i] = b1[i]; }
    __syncthreads();

    size_t e = (size_t)blockIdx.x * 8 + w;
    if (e >= EE) return;
    size_t i1 = (size_t)idx1[e], i2 = (size_t)idx2[e];
    const float* p1 = g_QKV + i1 * 192;
    const float* p2 = g_QKV + i2 * 192;
    float q0  = p1[l],        q1  = p1[l + 32];
    float k10 = p1[64 + l],   k11 = p1[96 + l];
    float v10 = p1[128 + l],  v11 = p1[160 + l];
    float k20 = p2[64 + l],   k21 = p2[96 + l];
    float v20 = p2[128 + l],  v21 = p2[160 + l];

    const float* ef = edge_fea + e * 64;
    efs[w][l] = ef[l]; efs[w][l + 32] = ef[l + 32];
    __syncwarp();
    float e0 = bEs[l], e1 = bEs[l + 32];
    #pragma unroll 8
    for (int k = 0; k < 64; k++) {
        float x = efs[w][k];
        e0 = fmaf(x, WEs[k * 64 + l], e0);
        e1 = fmaf(x, WEs[k * 64 + l + 32], e1);
    }

    const float inv = 0.07216878364870323f;  // 1/sqrt(192)
    float a[6], z[6];
    a[0] = q0 * k10 * inv; a[1] = q1 * k11 * inv;
    a[2] = q0 * k20 * inv; a[3] = q1 * k21 * inv;
    a[4] = q0 * e0  * inv; a[5] = q1 * e1  * inv;
    z[0] = v10; z[1] = v11; z[2] = v20; z[3] = v21; z[4] = e0; z[5] = e1;

    float s1 = 0.f, s2 = 0.f;
    #pragma unroll
    for (int i = 0; i < 6; i++) { s1 += a[i]; s2 += a[i] * a[i]; }
    #pragma unroll
    for (int o = 16; o; o >>= 1) {
        s1 += __shfl_xor_sync(0xFFFFFFFFu, s1, o);
        s2 += __shfl_xor_sync(0xFFFFFFFFu, s2, o);
    }
    float m = s1 * (1.f / 192.f);
    float var = s2 * (1.f / 192.f) - m * m;
    float r = rsqrtf(var + 1e-5f);

    float* Zp = g_Z + e * 192;
    float* Sp = g_S + e * 192;
    #pragma unroll
    for (int i = 0; i < 6; i++) {
        int j = l + 32 * i;
        float y = (a[i] - m) * r * g1s[j] + b1s[j];
        float sg = 1.f / (1.f + expf(-y));
        Zp[j] = z[i];
        Sp[j] = sg;
    }
}

// ---------------- K3: fused GEMM1 + gate + GEMM2 + LN + scatter ----------------
// block = 256 threads, tile = 64 edges. grid = EE/64 = 12500
#define TM 64
#define ZS 200   // padded stride for Z/mij tile
#define WS 200   // padded stride for weight k-tile
#define TS 132   // padded stride for T tile

__global__ __launch_bounds__(256) void k_mm(
        const float* __restrict__ Wu, const float* __restrict__ bu,
        const float* __restrict__ Wm, const float* __restrict__ bm,
        const float* __restrict__ g2, const float* __restrict__ b2,
        const int* __restrict__ idx1,
        float* __restrict__ out) {
    extern __shared__ float sm[];
    float* zs = sm;                 // TM*ZS   (Z tile, reused as mij)
    float* ws = zs + TM * ZS;       // 16*WS   (weight k-tile)
    float* ts = ws + 16 * WS;       // TM*TS   (T tile)

    int t = threadIdx.x;
    int tx = t & 15, ty = t >> 4;
    size_t e0 = (size_t)blockIdx.x * TM;

    // stage Z tile [64][192]
    for (int f = t; f < TM * 48; f += 256) {
        int r = f / 48, c = f % 48;
        float4 v = *(const float4*)(g_Z + (e0 + r) * 192 + c * 4);
        *(float4*)&zs[r * ZS + c * 4] = v;
    }
    __syncthreads();

    // ---- GEMM1: U = Z @ Wu ----
    float acc[4][12];
    #pragma unroll
    for (int r = 0; r < 4; r++)
        #pragma unroll
        for (int c = 0; c < 12; c++) acc[r][c] = 0.f;

    for (int kt = 0; kt < 192; kt += 16) {
        for (int f = t; f < 16 * 48; f += 256) {
            int r = f / 48, c = f % 48;
            float4 v = *(const float4*)(Wu + (size_t)(kt + r) * 192 + c * 4);
            *(float4*)&ws[r * WS + c * 4] = v;
        }
        __syncthreads();
        #pragma unroll 4
        for (int k = 0; k < 16; k++) {
            float av[4];
            #pragma unroll
            for (int r = 0; r < 4; r++) av[r] = zs[(ty * 4 + r) * ZS + kt + k];
            float4 b0 = *(float4*)&ws[k * WS + tx * 12];
            float4 b1 = *(float4*)&ws[k * WS + tx * 12 + 4];
            float4 b2v = *(float4*)&ws[k * WS + tx * 12 + 8];
            float bv[12] = {b0.x, b0.y, b0.z, b0.w, b1.x, b1.y, b1.z, b1.w,
                            b2v.x, b2v.y, b2v.z, b2v.w};
            #pragma unroll
            for (int r = 0; r < 4; r++)
                #pragma unroll
                for (int c = 0; c < 12; c++)
                    acc[r][c] = fmaf(av[r], bv[c], acc[r][c]);
        }
        __syncthreads();
    }

    // epilogue: mij = S * (U + bu), overwrite zs
    #pragma unroll
    for (int r = 0; r < 4; r++) {
        int e = ty * 4 + r;
        #pragma unroll
        for (int c = 0; c < 12; c++) {
            int col = tx * 12 + c;
            float u = acc[r][c] + bu[col];
            float s = g_S[(e0 + e) * 192 + col];
            acc[r][c] = s * u;
        }
    }
    __syncthreads();   // all zs reads done
    #pragma unroll
    for (int r = 0; r < 4; r++)
        #pragma unroll
        for (int c = 0; c < 12; c++)
            zs[(ty * 4 + r) * ZS + tx * 12 + c] = acc[r][c];
    __syncthreads();

    // ---- GEMM2: T = mij @ Wm ----
    float acc2[4][8];
    #pragma unroll
    for (int r = 0; r < 4; r++)
        #pragma unroll
        for (int c = 0; c < 8; c++) acc2[r][c] = 0.f;

    for (int kt = 0; kt < 192; kt += 16) {
        for (int f = t; f < 16 * 32; f += 256) {
            int r = f / 32, c = f % 32;
            float4 v = *(const float4*)(Wm + (size_t)(kt + r) * 128 + c * 4);
            *(float4*)&ws[r * WS + c * 4] = v;
        }
        __syncthreads();
        #pragma unroll 4
        for (int k = 0; k < 16; k++) {
            float av[4];
            #pragma unroll
            for (int r = 0; r < 4; r++) av[r] = zs[(ty * 4 + r) * ZS + kt + k];
            float4 b0 = *(float4*)&ws[k * WS + tx * 8];
            float4 b1 = *(float4*)&ws[k * WS + tx * 8 + 4];
            float bv[8] = {b0.x, b0.y, b0.z, b0.w, b1.x, b1.y, b1.z, b1.w};
            #pragma unroll
            for (int r = 0; r < 4; r++)
                #pragma unroll
                for (int c = 0; c < 8; c++)
                    acc2[r][c] = fmaf(av[r], bv[c], acc2[r][c]);
        }
        __syncthreads();
    }

    // stage T (+bm) to smem
    #pragma unroll
    for (int r = 0; r < 4; r++)
        #pragma unroll
        for (int c = 0; c < 8; c++) {
            int col = tx * 8 + c;
            ts[(ty * 4 + r) * TS + col] = acc2[r][c] + bm[col];
        }
    __syncthreads();

    // ---- row LN + atomic scatter ----
    int w = t >> 5, l = t & 31;
    float gg[4], bb[4];
    #pragma unroll
    for (int mth = 0; mth < 4; mth++) { gg[mth] = g2[l + 32 * mth]; bb[mth] = b2[l + 32 * mth]; }
    for (int rr = 0; rr < 8; rr++) {
        int e = w * 8 + rr;
        float x[4];
        #pragma unroll
        for (int mth = 0; mth < 4; mth++) x[mth] = ts[e * TS + l + 32 * mth];
        float s1 = x[0] + x[1] + x[2] + x[3];
        float s2 = x[0]*x[0] + x[1]*x[1] + x[2]*x[2] + x[3]*x[3];
        #pragma unroll
        for (int o = 16; o; o >>= 1) {
            s1 += __shfl_xor_sync(0xFFFFFFFFu, s1, o);
            s2 += __shfl_xor_sync(0xFFFFFFFFu, s2, o);
        }
        float m = s1 * (1.f / 128.f);
        float var = s2 * (1.f / 128.f) - m * m;
        float rinv = rsqrtf(var + 1e-5f);
        size_t n = (size_t)idx1[e0 + e];
        float* op = out + n * 128;
        #pragma unroll
        for (int mth = 0; mth < 4; mth++)
            atomicAdd(&op[l + 32 * mth], (x[mth] - m) * rinv * gg[mth] + bb[mth]);
    }
}

// ---------------- launch ----------------
extern "C" void kernel_launch(void* const* d_in, const int* in_sizes, int n_in,
                              void* d_out, int out_size) {
    const float* node_fea = (const float*)d_in[0];
    const int*   idx1     = (const int*)d_in[1];
    const int*   idx2     = (const int*)d_in[2];
    const float* edge_fea = (const float*)d_in[3];
    const float* WQ = (const float*)d_in[4];  const float* bQ = (const float*)d_in[5];
    const float* WK = (const float*)d_in[6];  const float* bK = (const float*)d_in[7];
    const float* WV = (const float*)d_in[8];  const float* bV = (const float*)d_in[9];
    const float* WE = (const float*)d_in[10]; const float* bE = (const float*)d_in[11];
    const float* Wu = (const float*)d_in[12]; const float* bu = (const float*)d_in[13];
    const float* Wm = (const float*)d_in[14]; const float* bm = (const float*)d_in[15];
    const float* g1 = (const float*)d_in[16]; const float* b1 = (const float*)d_in[17];
    const float* g2 = (const float*)d_in[18]; const float* b2 = (const float*)d_in[19];
    float* out = (float*)d_out;

    int smem_qkv = (128 * 192 + 192 + 128) * 4;                 // 99584 B
    int smem_mm  = (TM * ZS + 16 * WS + TM * TS) * 4;           // 97792 B
    cudaFuncSetAttribute(k_qkv, cudaFuncAttributeMaxDynamicSharedMemorySize, smem_qkv);
    cudaFuncSetAttribute(k_mm,  cudaFuncAttributeMaxDynamicSharedMemorySize, smem_mm);

    cudaMemsetAsync(out, 0, (size_t)out_size * sizeof(float));

    k_qkv<<<296, 256, smem_qkv>>>(node_fea, WQ, bQ, WK, bK, WV, bV);
    k_edge<<<EE / 8, 256>>>(idx1, idx2, edge_fea, WE, bE, g1, b1);
    k_mm<<<EE / TM, 256, smem_mm>>>(Wu, bu, Wm, bm, g2, b2, idx1, out);
}

// round 16
// speedup vs baseline: 1.0033x; 1.0033x over previous
#include <cuda_runtime.h>
#include <cstddef>

#define NN 50000
#define EE 800000
// DV=128, DE=64, DH=64, 3*DH=192

// ---------------- scratch ----------------
// node table: [n][0:64]=Q, [64:128]=K, [128:320]=A1=V@Wu1, [320:512]=A2=V@Wu2
__device__ float g_NT[(size_t)NN * 512];      // 102.4 MB
__device__ float g_Wnode[128 * 512];          // [WQ | WK | WV@Wu1 | WV@Wu2]
__device__ float g_bnode[512];
__device__ float g_Wfuse[64 * 256];           // [WE | WE@Wu3]
__device__ float g_b3[192];                   // bu + bE@Wu3

// ---------------- fold kernels (tiny) ----------------
__global__ void fold_node(const float* __restrict__ WQ, const float* __restrict__ bQ,
                          const float* __restrict__ WK, const float* __restrict__ bK,
                          const float* __restrict__ WV, const float* __restrict__ bV,
                          const float* __restrict__ Wu) {
    int k = blockIdx.x;        // 0..127
    int c = threadIdx.x;       // 0..191
    if (c < 64) {
        g_Wnode[k * 512 + c]      = WQ[k * 64 + c];
        g_Wnode[k * 512 + 64 + c] = WK[k * 64 + c];
    }
    float s1 = 0.f, s2 = 0.f;
    for (int j = 0; j < 64; j++) {
        float w = WV[k * 64 + j];
        s1 = fmaf(w, Wu[j * 192 + c], s1);
        s2 = fmaf(w, Wu[(64 + j) * 192 + c], s2);
    }
    g_Wnode[k * 512 + 128 + c] = s1;
    g_Wnode[k * 512 + 320 + c] = s2;
    if (k == 0) {
        if (c < 64) { g_bnode[c] = bQ[c]; g_bnode[64 + c] = bK[c]; }
        float t1 = 0.f, t2 = 0.f;
        for (int j = 0; j < 64; j++) {
            float b = bV[j];
            t1 = fmaf(b, Wu[j * 192 + c], t1);
            t2 = fmaf(b, Wu[(64 + j) * 192 + c], t2);
        }
        g_bnode[128 + c] = t1;
        g_bnode[320 + c] = t2;
    }
}

__global__ void fold_edge(const float* __restrict__ WE, const float* __restrict__ bE,
                          const float* __restrict__ Wu, const float* __restrict__ bu) {
    int k = blockIdx.x;        // 0..63
    int c = threadIdx.x;       // 0..191
    if (c < 64) g_Wfuse[k * 256 + c] = WE[k * 64 + c];
    float s = 0.f;
    for (int j = 0; j < 64; j++)
        s = fmaf(WE[k * 64 + j], Wu[(128 + j) * 192 + c], s);
    g_Wfuse[k * 256 + 64 + c] = s;
    if (k == 0) {
        float t = bu[c];
        for (int j = 0; j < 64; j++)
            t = fmaf(bE[j], Wu[(128 + j) * 192 + c], t);
        g_b3[c] = t;
    }
}

// ---------------- node-table GEMM: NT = X @ Wnode + bnode ----------------
// grid (782, 2): 64 nodes x 256 cols per block, k=128 in chunks of 16
#define NXS 132
#define NWS 260
__global__ __launch_bounds__(256) void k_node(const float* __restrict__ X) {
    extern __shared__ float sm[];
    float* xs = sm;              // [64][NXS]
    float* ws = xs + 64 * NXS;   // [16][NWS]
    int t = threadIdx.x, tx = t & 15, ty = t >> 4;
    int n0 = blockIdx.x * 64;
    int c0 = blockIdx.y * 256;

    for (int f = t; f < 64 * 32; f += 256) {
        int r = f >> 5, c4 = f & 31;
        int n = n0 + r;
        float4 v = (n < NN) ? *(const float4*)(X + (size_t)n * 128 + c4 * 4)
                            : make_float4(0.f, 0.f, 0.f, 0.f);
        *(float4*)&xs[r * NXS + c4 * 4] = v;
    }
    __syncthreads();

    float acc[4][16];
    #pragma unroll
    for (int r = 0; r < 4; r++)
        #pragma unroll
        for (int c = 0; c < 16; c++) acc[r][c] = 0.f;

    for (int kt = 0; kt < 128; kt += 16) {
        for (int f = t; f < 16 * 64; f += 256) {
            int r = f >> 6, c4 = f & 63;
            float4 v = *(const float4*)(g_Wnode + (size_t)(kt + r) * 512 + c0 + c4 * 4);
            *(float4*)&ws[r * NWS + c4 * 4] = v;
        }
        __syncthreads();
        #pragma unroll 4
        for (int k = 0; k < 16; k++) {
            float av[4];
            #pragma unroll
            for (int r = 0; r < 4; r++) av[r] = xs[(ty * 4 + r) * NXS + kt + k];
            float bv[16];
            #pragma unroll
            for (int c4 = 0; c4 < 4; c4++)
                *(float4*)&bv[c4 * 4] = *(float4*)&ws[k * NWS + tx * 16 + c4 * 4];
            #pragma unroll
            for (int r = 0; r < 4; r++)
                #pragma unroll
                for (int c = 0; c < 16; c++)
                    acc[r][c] = fmaf(av[r], bv[c], acc[r][c]);
        }
        __syncthreads();
    }

    #pragma unroll
    for (int r = 0; r < 4; r++) {
        int n = n0 + ty * 4 + r;
        if (n < NN) {
            #pragma unroll
            for (int c = 0; c < 16; c++) {
                int col = c0 + tx * 16 + c;
                g_NT[(size_t)n * 512 + col] = acc[r][c] + g_bnode[col];
            }
        }
    }
}

// ---------------- fused edge kernel ----------------
// 64-edge tile per block (256 thr). Stage A: P = ef@Wfuse [64][256].
// Middle: gather + gate -> m in P[:,0:192]. Stage B: T = m@Wm -> LN -> scatter.
#define PS 264
#define EFS 68
#define WS2 260

__global__ __launch_bounds__(256) void k_fused(
        const int* __restrict__ idx1, const int* __restrict__ idx2,
        const float* __restrict__ edge_fea,
        const float* __restrict__ bE,
        const float* __restrict__ g1, const float* __restrict__ b1,
        const float* __restrict__ Wm, const float* __restrict__ bm,
        const float* __restrict__ g2, const float* __restrict__ b2,
        float* __restrict__ out) {
    extern __shared__ float sm[];
    float* P   = sm;                 // [64][PS]
    float* efs = P + 64 * PS;        // [64][EFS]
    float* ws  = efs + 64 * EFS;     // [16][WS2]
    float* bEs = ws + 16 * WS2;      // [64]
    float* b3s = bEs + 64;           // [192]
    float* g1s = b3s + 192;          // [192]
    float* b1s = g1s + 192;          // [192]
    int*   is1 = (int*)(b1s + 192);  // [64]
    int*   is2 = is1 + 64;           // [64]

    int t = threadIdx.x, tx = t & 15, ty = t >> 4;
    int w = t >> 5, l = t & 31;
    size_t e0 = (size_t)blockIdx.x * 64;

    // load small vectors + indices + ef tile
    if (t < 64)  bEs[t] = bE[t];
    if (t < 192) { b3s[t] = g_b3[t]; g1s[t] = g1[t]; b1s[t] = b1[t]; }
    if (t < 64)  { is1[t] = idx1[e0 + t]; is2[t] = idx2[e0 + t]; }
    for (int f = t; f < 64 * 16; f += 256) {
        int r = f >> 4, c4 = f & 15;
        float4 v = *(const float4*)(edge_fea + (e0 + r) * 64 + c4 * 4);
        *(float4*)&efs[r * EFS + c4 * 4] = v;
    }
    __syncthreads();

    // ---- Stage A: P = ef @ Wfuse  (64x256, k=64) ----
    float acc[4][16];
    #pragma unroll
    for (int r = 0; r < 4; r++)
        #pragma unroll
        for (int c = 0; c < 16; c++) acc[r][c] = 0.f;

    for (int kt = 0; kt < 64; kt += 16) {
        for (int f = t; f < 16 * 64; f += 256) {
            int r = f >> 6, c4 = f & 63;
            float4 v = *(const float4*)(g_Wfuse + (size_t)(kt + r) * 256 + c4 * 4);
            *(float4*)&ws[r * WS2 + c4 * 4] = v;
        }
        __syncthreads();
        #pragma unroll 4
        for (int k = 0; k < 16; k++) {
            float av[4];
            #pragma unroll
            for (int r = 0; r < 4; r++) av[r] = efs[(ty * 4 + r) * EFS + kt + k];
            float bv[16];
            #pragma unroll
            for (int c4 = 0; c4 < 4; c4++)
                *(float4*)&bv[c4 * 4] = *(float4*)&ws[k * WS2 + tx * 16 + c4 * 4];
            #pragma unroll
            for (int r = 0; r < 4; r++)
                #pragma unroll
                for (int c = 0; c < 16; c++)
                    acc[r][c] = fmaf(av[r], bv[c], acc[r][c]);
        }
        __syncthreads();
    }
    #pragma unroll
    for (int r = 0; r < 4; r++)
        #pragma unroll
        for (int c = 0; c < 16; c++)
            P[(ty * 4 + r) * PS + tx * 16 + c] = acc[r][c];
    __syncthreads();

    // ---- Middle: per-row gather + gate (warp per row, 8 rows/warp) ----
    const float inv = 0.07216878364870323f;  // 1/sqrt(192)
    for (int ri = 0; ri < 8; ri++) {
        int r = w * 8 + ri;
        const float* t1 = g_NT + (size_t)is1[r] * 512;
        const float* t2 = g_NT + (size_t)is2[r] * 512;
        float q0  = t1[l],       q1  = t1[l + 32];
        float k10 = t1[64 + l],  k11 = t1[96 + l];
        float k20 = t2[64 + l],  k21 = t2[96 + l];
        float ep0 = P[r * PS + l]      + bEs[l];
        float ep1 = P[r * PS + l + 32] + bEs[l + 32];

        float a[6], u[6];
        a[0] = q0 * k10 * inv; a[1] = q1 * k11 * inv;
        a[2] = q0 * k20 * inv; a[3] = q1 * k21 * inv;
        a[4] = q0 * ep0 * inv; a[5] = q1 * ep1 * inv;
        #pragma unroll
        for (int i = 0; i < 6; i++) {
            int j = l + 32 * i;
            u[i] = P[r * PS + 64 + j] + t1[128 + j] + t2[320 + j] + b3s[j];
        }

        float s1 = 0.f, s2 = 0.f;
        #pragma unroll
        for (int i = 0; i < 6; i++) { s1 += a[i]; s2 += a[i] * a[i]; }
        #pragma unroll
        for (int o = 16; o; o >>= 1) {
            s1 += __shfl_xor_sync(0xFFFFFFFFu, s1, o);
            s2 += __shfl_xor_sync(0xFFFFFFFFu, s2, o);
        }
        float m = s1 * (1.f / 192.f);
        float var = s2 * (1.f / 192.f) - m * m;
        float rinv = rsqrtf(var + 1e-5f);

        float mv[6];
        #pragma unroll
        for (int i = 0; i < 6; i++) {
            int j = l + 32 * i;
            float y = (a[i] - m) * rinv * g1s[j] + b1s[j];
            mv[i] = u[i] / (1.f + expf(-y));
        }
        __syncwarp();
        #pragma unroll
        for (int i = 0; i < 6; i++) P[r * PS + l + 32 * i] = mv[i];
    }
    __syncthreads();

    // ---- Stage B: T = m @ Wm  (64x128, k=192) ----
    float acc2[4][8];
    #pragma unroll
    for (int r = 0; r < 4; r++)
        #pragma unroll
        for (int c = 0; c < 8; c++) acc2[r][c] = 0.f;

    for (int kt = 0; kt < 192; kt += 16) {
        for (int f = t; f < 16 * 32; f += 256) {
            int r = f >> 5, c4 = f & 31;
            float4 v = *(const float4*)(Wm + (size_t)(kt + r) * 128 + c4 * 4);
            *(float4*)&ws[r * WS2 + c4 * 4] = v;
        }
        __syncthreads();
        #pragma unroll 4
        for (int k = 0; k < 16; k++) {
            float av[4];
            #pragma unroll
            for (int r = 0; r < 4; r++) av[r] = P[(ty * 4 + r) * PS + kt + k];
            float bv[8];
            *(float4*)&bv[0] = *(float4*)&ws[k * WS2 + tx * 8];
            *(float4*)&bv[4] = *(float4*)&ws[k * WS2 + tx * 8 + 4];
            #pragma unroll
            for (int r = 0; r < 4; r++)
                #pragma unroll
                for (int c = 0; c < 8; c++)
                    acc2[r][c] = fmaf(av[r], bv[c], acc2[r][c]);
        }
        __syncthreads();
    }

    // ---- row LN (16-lane groups) + atomic scatter ----
    float bmv[8], g2v[8], b2v[8];
    #pragma unroll
    for (int c = 0; c < 8; c++) {
        int col = tx * 8 + c;
        bmv[c] = bm[col]; g2v[c] = g2[col]; b2v[c] = b2[col];
    }
    #pragma unroll
    for (int r = 0; r < 4; r++) {
        float s1 = 0.f, s2 = 0.f;
        #pragma unroll
        for (int c = 0; c < 8; c++) {
            float x = acc2[r][c] + bmv[c];
            acc2[r][c] = x;
            s1 += x; s2 += x * x;
        }
        #pragma unroll
        for (int o = 8; o; o >>= 1) {
            s1 += __shfl_xor_sync(0xFFFFFFFFu, s1, o);
            s2 += __shfl_xor_sync(0xFFFFFFFFu, s2, o);
        }
        float m = s1 * (1.f / 128.f);
        float var = s2 * (1.f / 128.f) - m * m;
        float rinv = rsqrtf(var + 1e-5f);
        int row = ty * 4 + r;
        float* op = out + (size_t)is1[row] * 128 + tx * 8;
        #pragma unroll
        for (int c = 0; c < 8; c++)
            atomicAdd(&op[c], (acc2[r][c] - m) * rinv * g2v[c] + b2v[c]);
    }
}

// ---------------- launch ----------------
extern "C" void kernel_launch(void* const* d_in, const int* in_sizes, int n_in,
                              void* d_out, int out_size) {
    const float* node_fea = (const float*)d_in[0];
    const int*   idx1     = (const int*)d_in[1];
    const int*   idx2     = (const int*)d_in[2];
    const float* edge_fea = (const float*)d_in[3];
    const float* WQ = (const float*)d_in[4];  const float* bQ = (const float*)d_in[5];
    const float* WK = (const float*)d_in[6];  const float* bK = (const float*)d_in[7];
    const float* WV = (const float*)d_in[8];  const float* bV = (const float*)d_in[9];
    const float* WE = (const float*)d_in[10]; const float* bE = (const float*)d_in[11];
    const float* Wu = (const float*)d_in[12]; const float* bu = (const float*)d_in[13];
    const float* Wm = (const float*)d_in[14]; const float* bm = (const float*)d_in[15];
    const float* g1 = (const float*)d_in[16]; const float* b1 = (const float*)d_in[17];
    const float* g2 = (const float*)d_in[18]; const float* b2 = (const float*)d_in[19];
    float* out = (float*)d_out;

    int smem_node  = (64 * NXS + 16 * NWS) * 4;                       // 50432
    int smem_fused = (64 * PS + 64 * EFS + 16 * WS2 + 64 + 192 * 3) * 4 + 128 * 4;
    cudaFuncSetAttribute(k_node,  cudaFuncAttributeMaxDynamicSharedMemorySize, smem_node);
    cudaFuncSetAttribute(k_fused, cudaFuncAttributeMaxDynamicSharedMemorySize, smem_fused);

    cudaMemsetAsync(out, 0, (size_t)out_size * sizeof(float));

    fold_node<<<128, 192>>>(WQ, bQ, WK, bK, WV, bV, Wu);
    fold_edge<<<64, 192>>>(WE, bE, Wu, bu);
    k_node<<<dim3((NN + 63) / 64, 2), 256, smem_node>>>(node_fea);
    k_fused<<<EE / 64, 256, smem_fused>>>(idx1, idx2, edge_fea, bE, g1, b1,
                                          Wm, bm, g2, b2, out);
}